// round 10
// baseline (speedup 1.0000x reference)
#include <cuda_runtime.h>

// Dynamic per-pixel 5x5 conv (KPN) + leaky_relu(0.2), replicate padding.
// x:      (N=4, C=8, H=256, W=256) f32   -> d_in[0]
// kernel: (N=4, C*25=200, H=256, W=256)  -> d_in[1]
// out:    (N=4, C=8, H=256, W=256) f32
//
// R10: launch_bounds (128,6) -> 85-reg budget, ~24 warps/SM. All 10 kernel
// float4 loads per x-row batched into registers BEFORE the FMA block: a
// clean 10-deep LDG.128 pipeline per iteration (~11 in flight per warp).
// Occupancy trades down but total in-flight DRAM bytes rise ~20%.

#define NN   4
#define CC   8
#define HH   256
#define WW   256
#define KK   5
#define PAD  2
#define NEG_SLOPE 0.2f

#define W4   (WW / 4)           // 64
#define HW4  (HH * W4)          // 16384 float4 per plane
#define H2   (HH / 2)           // 128 row-pairs
#define TOTAL_THREADS (NN * CC * H2 * W4)   // 262144
#define BLOCK 128

__device__ __forceinline__ float lrelu(float v) {
    return v >= 0.f ? v : NEG_SLOPE * v;
}

__global__ __launch_bounds__(BLOCK, 6) void dynconv_kernel(
    const float* __restrict__ x,
    const float* __restrict__ ker,
    float* __restrict__ out)
{
    int tid = blockIdx.x * BLOCK + threadIdx.x;

    int w4   = tid & (W4 - 1);
    int hblk = (tid >> 6) & (H2 - 1);
    int nc   = tid >> 13;               // 0 .. N*C-1 (32)
    int h0   = hblk << 1;               // even row
    int w0   = w4 << 2;

    const float* xbase = x + (size_t)nc * (HH * WW);
    const float4* kbase0 = reinterpret_cast<const float4*>(ker)
                         + (size_t)nc * 25 * HW4
                         + (size_t)h0 * W4 + w4;
    const float4* kbase1 = kbase0 + W4;   // row h0+1

    // Accumulators: b -> row h0, c -> row h0+1
    float b0 = 0.f, b1 = 0.f, b2 = 0.f, b3 = 0.f;
    float c0 = 0.f, c1 = 0.f, c2 = 0.f, c3 = 0.f;

    // x rows h0-2 .. h0+3 serve taps of both output rows.
    #pragma unroll
    for (int rr = 0; rr < KK + 1; rr++) {
        int r = h0 + rr - PAD;
        r = max(0, min(HH - 1, r));
        const float* row = xbase + r * WW;

        float xv[8];
        #pragma unroll
        for (int i = 0; i < 8; i++) {
            int cidx = w0 + i - PAD;
            cidx = max(0, min(WW - 1, cidx));
            xv[i] = __ldg(row + cidx);
        }

        // Batch ALL kernel plane loads for this x-row first (10-deep LDG.128
        // pipeline), then do the FMAs.
        float4 kv0[KK], kv1[KK];
        #pragma unroll
        for (int k2 = 0; k2 < KK; k2++) {
            if (rr < KK)
                kv0[k2] = __ldcs(kbase0 + (size_t)(rr * KK + k2) * HW4);
            if (rr >= 1)
                kv1[k2] = __ldcs(kbase1 + (size_t)((rr - 1) * KK + k2) * HW4);
        }

        #pragma unroll
        for (int k2 = 0; k2 < KK; k2++) {
            if (rr < KK) {
                b0 = fmaf(xv[k2 + 0], kv0[k2].x, b0);
                b1 = fmaf(xv[k2 + 1], kv0[k2].y, b1);
                b2 = fmaf(xv[k2 + 2], kv0[k2].z, b2);
                b3 = fmaf(xv[k2 + 3], kv0[k2].w, b3);
            }
            if (rr >= 1) {
                c0 = fmaf(xv[k2 + 0], kv1[k2].x, c0);
                c1 = fmaf(xv[k2 + 1], kv1[k2].y, c1);
                c2 = fmaf(xv[k2 + 2], kv1[k2].z, c2);
                c3 = fmaf(xv[k2 + 3], kv1[k2].w, c3);
            }
        }
    }

    float4 ob, oc;
    ob.x = lrelu(b0); ob.y = lrelu(b1); ob.z = lrelu(b2); ob.w = lrelu(b3);
    oc.x = lrelu(c0); oc.y = lrelu(c1); oc.z = lrelu(c2); oc.w = lrelu(c3);

    float4* out4 = reinterpret_cast<float4*>(out);
    size_t obase = (size_t)nc * HW4 + (size_t)h0 * W4 + w4;
    out4[obase]      = ob;
    out4[obase + W4] = oc;
}

extern "C" void kernel_launch(void* const* d_in, const int* in_sizes, int n_in,
                              void* d_out, int out_size)
{
    const float* x   = (const float*)d_in[0];
    const float* ker = (const float*)d_in[1];
    float* out = (float*)d_out;

    dynconv_kernel<<<TOTAL_THREADS / BLOCK, BLOCK>>>(x, ker, out);
}